// round 11
// baseline (speedup 1.0000x reference)
#include <cuda_runtime.h>

// GlottalFlowTable — fixed shapes: B=32, S=524288, HOP=256, L=100, frames=2048
//
// R11 = R10 optimum + table-row L1 prefetch.
// Diagnosis: issue=47% @ occ=84% matches a ~900-cyc dependency chain
// (wp DRAM load -> indices -> ~50%-L1-miss gathers -> math). Table row
// addresses are wp-independent, so prefetch.global.L1 both rows (2 x 400B,
// warp-uniform) BEFORE the wp load: table L2 latency hides under the wp
// DRAM latency and the 16 gathers become L1 hits, shortening the chain.
// Gather structure itself untouched — it sits at the L1TEX wavefront floor
// (19.5us, verified three rounds running).

constexpr int B      = 32;
constexpr int S      = 524288;
constexpr int HOP    = 256;
constexpr int L      = 100;
constexpr int FRAMES = S / HOP;    // 2048
constexpr int TROWS  = FRAMES + 1; // 2049
constexpr int S4     = S / 4;      // 131072 float4 per batch row

__global__ __launch_bounds__(256)
void glottal_flow_kernel(const float* __restrict__ wp,
                         const float* __restrict__ tables,
                         float* __restrict__ out)
{
    int i4 = blockIdx.x * 256 + threadIdx.x;   // global float4 index
    int b  = i4 >> 17;                         // / S4 (131072)
    int s  = (i4 & (S4 - 1)) << 2;             // sample index within batch row
    int f  = s >> 8;                           // frame (HOP = 256)
    int t  = s & (HOP - 1);                    // position within frame

    const float* rowF = tables + (size_t)(b * TROWS + f) * L; // floor frame row
    const float* rowC = rowF + L;                              // ceil frame row

    // Prefetch both table rows into L1 before the (long-latency) wp load.
    // A warp's 128 samples lie inside one frame, so rowF/rowC are
    // warp-uniform; lanes 0-9 cover all cache lines of both 400B rows
    // (element offsets 0,32,64,96,99) with a single predicated instruction.
    {
        int lane = threadIdx.x & 31;
        if (lane < 10) {
            int e = (lane >= 5 ? lane - 5 : lane) * 32;
            e = min(e, L - 1);
            const float* pp = (lane >= 5 ? rowC : rowF) + e;
            asm volatile("prefetch.global.L1 [%0];" :: "l"(pp));
        }
    }

    float4 w = __ldcs(reinterpret_cast<const float4*>(wp) + i4);  // streaming

    float wk[4] = {w.x, w.y, w.z, w.w};
    float r[4];

#pragma unroll
    for (int k = 0; k < 4; ++k) {
        float idx_raw = wk[k] * (float)L;
        int   fi      = (int)idx_raw;              // trunc toward zero (data >= 0)
        fi            = max(0, min(fi, L - 1));    // clip like reference
        float p       = idx_raw - (float)fi;
        int   fj      = fi + 1;
        if (fj == L) fj = 0;                       // padded column L == column 0

        float loF = __ldg(rowF + fi);
        float hiF = __ldg(rowF + fj);
        float loC = __ldg(rowC + fi);
        float hiC = __ldg(rowC + fj);

        float vF = fmaf(p, hiF - loF, loF);        // phase lerp, floor frame
        float vC = fmaf(p, hiC - loC, loC);        // phase lerp, ceil frame
        float p2 = (float)(t + k) * (1.0f / (float)HOP);
        r[k] = fmaf(p2, vC - vF, vF);              // frame lerp
    }

    __stcs(reinterpret_cast<float4*>(out) + i4,    // streaming store
           make_float4(r[0], r[1], r[2], r[3]));
}

extern "C" void kernel_launch(void* const* d_in, const int* in_sizes, int n_in,
                              void* d_out, int out_size)
{
    const float* wp     = (const float*)d_in[0];
    const float* tables = (const float*)d_in[1];
    float*       out    = (float*)d_out;

    constexpr int total4 = (B * S) / 4;            // 4,194,304 float4 work items
    glottal_flow_kernel<<<total4 / 256, 256>>>(wp, tables, out);
}

// round 12
// speedup vs baseline: 1.0503x; 1.0503x over previous
#include <cuda_runtime.h>

// GlottalFlowTable — fixed shapes: B=32, S=524288, HOP=256, L=100, frames=2048
//
// FINAL (= R7/R9/R10, measured 28.6-29.4us kernel across four runs).
// 4 samples/thread, per-sample scalar-LDG bilinear gather, float4 streaming
// I/O (__ldcs wp, __stcs out), independent per-k FMA trees.
//
// Established floor (R1-R11 evidence):
//  - L1TEX wavefront floor ~19.5us; measured busy = 0.68 x 28.7 ✓ (3 runs)
//  - kernel is L1TEX-queueing bound at ~68% density: invariant to occupancy
//    (45-85%, R4/R5), batch shape (R4), prefetching (R11 raised issue 47->54
//    with zero duration change)
//  - all alternative gather units measured worse: shuffle 45us (R2), smem
//    quad 33.6us (R3); scratch repacks cost more DRAM than they save;
//    repackings are wavefront-invariant at 4B granularity
//  - R8 micro-variants (incremental p2, cached wp) regressed to 30.6us

constexpr int B      = 32;
constexpr int S      = 524288;
constexpr int HOP    = 256;
constexpr int L      = 100;
constexpr int FRAMES = S / HOP;    // 2048
constexpr int TROWS  = FRAMES + 1; // 2049
constexpr int S4     = S / 4;      // 131072 float4 per batch row

__global__ __launch_bounds__(256)
void glottal_flow_kernel(const float* __restrict__ wp,
                         const float* __restrict__ tables,
                         float* __restrict__ out)
{
    int i4 = blockIdx.x * 256 + threadIdx.x;   // global float4 index
    int b  = i4 >> 17;                         // / S4 (131072)
    int s  = (i4 & (S4 - 1)) << 2;             // sample index within batch row
    int f  = s >> 8;                           // frame (HOP = 256)
    int t  = s & (HOP - 1);                    // position within frame

    float4 w = __ldcs(reinterpret_cast<const float4*>(wp) + i4);  // streaming

    const float* rowF = tables + (size_t)(b * TROWS + f) * L; // floor frame row
    const float* rowC = rowF + L;                              // ceil frame row

    float wk[4] = {w.x, w.y, w.z, w.w};
    float r[4];

#pragma unroll
    for (int k = 0; k < 4; ++k) {
        float idx_raw = wk[k] * (float)L;
        int   fi      = (int)idx_raw;              // trunc toward zero (data >= 0)
        fi            = max(0, min(fi, L - 1));    // clip like reference
        float p       = idx_raw - (float)fi;
        int   fj      = fi + 1;
        if (fj == L) fj = 0;                       // padded column L == column 0

        float loF = __ldg(rowF + fi);
        float hiF = __ldg(rowF + fj);
        float loC = __ldg(rowC + fi);
        float hiC = __ldg(rowC + fj);

        float vF = fmaf(p, hiF - loF, loF);        // phase lerp, floor frame
        float vC = fmaf(p, hiC - loC, loC);        // phase lerp, ceil frame
        float p2 = (float)(t + k) * (1.0f / (float)HOP);
        r[k] = fmaf(p2, vC - vF, vF);              // frame lerp
    }

    __stcs(reinterpret_cast<float4*>(out) + i4,    // streaming store
           make_float4(r[0], r[1], r[2], r[3]));
}

extern "C" void kernel_launch(void* const* d_in, const int* in_sizes, int n_in,
                              void* d_out, int out_size)
{
    const float* wp     = (const float*)d_in[0];
    const float* tables = (const float*)d_in[1];
    float*       out    = (float*)d_out;

    constexpr int total4 = (B * S) / 4;            // 4,194,304 float4 work items
    glottal_flow_kernel<<<total4 / 256, 256>>>(wp, tables, out);
}